// round 2
// baseline (speedup 1.0000x reference)
#include <cuda_runtime.h>
#include <math.h>

#define NB   2048
#define NTHR 512

// ---------------- global scratch (static device arrays: allowed) ------------
__device__ float2 g_psi[NB * 4 * 10];                 // encoded per-wire vectors
__device__ float2 g_Elay[8 * 100];                    // merged layer 10x10 gates
__device__ __align__(16) float2 g_CX[10000];          // CX 100x100 (row-major [out][in])
__device__ __align__(16) float2 g_BS[10000];          // BS 100x100

__device__ const int c_gm1[10] = {0,0,0,1,1,2, 0,1,2,3};
__device__ const int c_gm2[10] = {1,2,3,2,3,3, 1,2,3,0};

// ---------------- complex helpers -------------------------------------------
__device__ __forceinline__ float2 cmul(float2 a, float2 b) {
    return make_float2(a.x * b.x - a.y * b.y, a.x * b.y + a.y * b.x);
}
__device__ __forceinline__ void cmacc(float2& acc, float2 a, float2 b) {
    acc.x = fmaf(a.x, b.x, fmaf(-a.y, b.y, acc.x));
    acc.y = fmaf(a.x, b.y, fmaf( a.y, b.x, acc.y));
}
__device__ __forceinline__ int strd(int w) {
    return w == 0 ? 1000 : (w == 1 ? 100 : (w == 2 ? 10 : 1));
}

// ---------------- 10x10 expm (block-cooperative, >=128 thr) ------------------
__device__ void expm10(float2* X, float2* S, float2* T, float2* T2, float* red, int t) {
    if (t < 10) {
        float s = 0.f;
        for (int j = 0; j < 10; j++) { float2 v = X[t * 10 + j]; s += fabsf(v.x) + fabsf(v.y); }
        red[t] = s;
    }
    __syncthreads();
    if (t == 0) {
        float m = 0.f;
        for (int i = 0; i < 10; i++) m = fmaxf(m, red[i]);
        int s = 0;
        while (m > 0.5f && s < 40) { m *= 0.5f; s++; }
        red[10] = (float)s;
    }
    __syncthreads();
    int s = (int)red[10];
    float sc = ldexpf(1.f, -s);
    if (t < 100) {
        X[t].x *= sc; X[t].y *= sc;
        T[t] = X[t];
        float2 v = X[t];
        if (t % 11 == 0) v.x += 1.f;   // diagonal for t<100
        S[t] = v;
    }
    __syncthreads();
    for (int j = 2; j <= 13; j++) {
        float inv = 1.f / (float)j;
        if (t < 100) {
            int i = t / 10, c = t % 10;
            float2 acc = make_float2(0.f, 0.f);
#pragma unroll
            for (int k = 0; k < 10; k++) cmacc(acc, T[i * 10 + k], X[k * 10 + c]);
            T2[t] = make_float2(acc.x * inv, acc.y * inv);
        }
        __syncthreads();
        if (t < 100) { T[t] = T2[t]; S[t].x += T2[t].x; S[t].y += T2[t].y; }
        __syncthreads();
    }
    for (int it = 0; it < s; it++) {
        if (t < 100) {
            int i = t / 10, c = t % 10;
            float2 acc = make_float2(0.f, 0.f);
#pragma unroll
            for (int k = 0; k < 10; k++) cmacc(acc, S[i * 10 + k], S[k * 10 + c]);
            T2[t] = acc;
        }
        __syncthreads();
        if (t < 100) S[t] = T2[t];
        __syncthreads();
    }
}

// ---------------- prep: encoding vectors + layer 10x10 gates -----------------
__global__ void k_enc(const float* __restrict__ jets, const float* __restrict__ s_scale,
                      const float* __restrict__ dmag, const float* __restrict__ dph,
                      const float* __restrict__ smag, const float* __restrict__ sph) {
    __shared__ float2 B0[100], B1[100], B2[100], B3[100], B4[100];
    __shared__ float red[16];
    int t = threadIdx.x;
    int id = blockIdx.x;

    float r_s, p_s, r_d, p_d;
    if (id < NB * 4) {
        const float* j3 = jets + id * 3;
        float eta = j3[0], ph = j3[1], pt = j3[2];
        float sc = 10.f / (1.f + expf(-s_scale[0])) + 0.01f;
        r_s = eta;      p_s = pt * ph * 0.5f;
        r_d = sc * pt;  p_d = eta;
    } else {
        int lw = id - NB * 4;                  // L*4+w
        r_s = smag[lw]; p_s = sph[lw];
        r_d = dmag[lw]; p_d = dph[lw];
    }

    // squeeze generator: 0.5*(conj(z)*a^2 - z*ad^2)
    float2 z = make_float2(r_s * cosf(p_s), r_s * sinf(p_s));
    if (t < 100) {
        int i = t / 10, j = t % 10;
        float2 g = make_float2(0.f, 0.f);
        if (j == i + 2) {
            float v = sqrtf((float)((i + 1) * (i + 2)));
            g.x = 0.5f * z.x * v;  g.y = -0.5f * z.y * v;
        } else if (i == j + 2) {
            float v = sqrtf((float)((j + 1) * (j + 2)));
            g.x = -0.5f * z.x * v; g.y = -0.5f * z.y * v;
        }
        B0[t] = g;
    }
    __syncthreads();
    expm10(B0, B1, B2, B3, red, t);            // squeeze exp -> B1
    __syncthreads();

    // displacement generator: al*ad - conj(al)*a
    float2 al = make_float2(r_d * cosf(p_d), r_d * sinf(p_d));
    if (t < 100) {
        int i = t / 10, j = t % 10;
        float2 g = make_float2(0.f, 0.f);
        if (i == j + 1) {
            float v = sqrtf((float)(j + 1));
            g.x = al.x * v;  g.y = al.y * v;
        } else if (j == i + 1) {
            float v = sqrtf((float)(i + 1));
            g.x = -al.x * v; g.y = al.y * v;
        }
        B0[t] = g;
    }
    __syncthreads();
    expm10(B0, B4, B2, B3, red, t);            // disp exp -> B4
    __syncthreads();

    if (id < NB * 4) {
        if (t < 10) {                          // psi = D @ S[:,0]
            float2 acc = make_float2(0.f, 0.f);
#pragma unroll
            for (int k = 0; k < 10; k++) cmacc(acc, B4[t * 10 + k], B1[k * 10 + 0]);
            g_psi[id * 10 + t] = acc;
        }
    } else {
        if (t < 100) {                         // E = D @ S
            int i = t / 10, j = t % 10;
            float2 acc = make_float2(0.f, 0.f);
#pragma unroll
            for (int k = 0; k < 10; k++) cmacc(acc, B4[i * 10 + k], B1[k * 10 + j]);
            g_Elay[(id - NB * 4) * 100 + t] = acc;
        }
    }
}

// ---------------- prep: 100x100 expm of CX / BS ------------------------------
__global__ void k_const100() {
    extern __shared__ float2 sh2[];
    float2* X = sh2;            // 10000
    float2* T = sh2 + 10000;    // 10000
    __shared__ float red[128];
    int t = threadIdx.x;
    int m = blockIdx.x;                        // 0 = CX, 1 = BS
    float2* gS = (m == 0) ? g_CX : g_BS;
    const float PIO4 = 0.7853981633974483f;

    for (int e = t; e < 10000; e += NTHR) {
        int o = e / 100, in = e % 100;
        int i = o / 10, j = o % 10, k = in / 10, l = in % 10;
        float2 g = make_float2(0.f, 0.f);
        if (m == 0) {
            float x1 = 0.f;
            if (k == i + 1) x1 = sqrtf((float)(i + 1));
            else if (i == k + 1) x1 = sqrtf((float)(k + 1));
            float y1 = 0.f;
            if (l == j + 1) y1 += sqrtf((float)(j + 1));
            if (j == l + 1) y1 -= sqrtf((float)(l + 1));
            g.x = -0.5f * x1 * y1;
        } else {
            float v = 0.f;
            if (k == i + 1 && j == l + 1) v += sqrtf((float)(i + 1)) * sqrtf((float)(l + 1));
            if (i == k + 1 && l == j + 1) v += sqrtf((float)(k + 1)) * sqrtf((float)(j + 1));
            g.y = PIO4 * v;
        }
        X[e] = g;
    }
    __syncthreads();

    if (t < 100) {
        float s = 0.f;
        for (int q = 0; q < 100; q++) { float2 v = X[t * 100 + q]; s += fabsf(v.x) + fabsf(v.y); }
        red[t] = s;
    }
    __syncthreads();
    if (t == 0) {
        float mx = 0.f;
        for (int i = 0; i < 100; i++) mx = fmaxf(mx, red[i]);
        int s = 0;
        while (mx > 0.5f && s < 40) { mx *= 0.5f; s++; }
        red[0] = (float)s;
    }
    __syncthreads();
    int s = (int)red[0];
    float scf = ldexpf(1.f, -s);

    for (int e = t; e < 10000; e += NTHR) {
        X[e].x *= scf; X[e].y *= scf;
        T[e] = X[e];
        float2 si = X[e];
        if (e / 100 == e % 100) si.x += 1.f;
        gS[e] = si;
    }
    __syncthreads();

    int c = t % 100, rb = t / 100;             // t<500 active in matmuls
    // Taylor terms
    for (int j = 2; j <= 13; j++) {
        float inv = 1.f / (float)j;
        float2 acc[20];
        if (t < 500) {
#pragma unroll
            for (int q = 0; q < 20; q++) acc[q] = make_float2(0.f, 0.f);
            for (int k = 0; k < 100; k++) {
                float2 xv = X[k * 100 + c];
#pragma unroll
                for (int q = 0; q < 20; q++) cmacc(acc[q], T[(rb * 20 + q) * 100 + k], xv);
            }
        }
        __syncthreads();
        if (t < 500) {
#pragma unroll
            for (int q = 0; q < 20; q++) {
                int r = rb * 20 + q;
                float2 v = make_float2(acc[q].x * inv, acc[q].y * inv);
                T[r * 100 + c] = v;
                float2 sv = gS[r * 100 + c];
                sv.x += v.x; sv.y += v.y;
                gS[r * 100 + c] = sv;
            }
        }
        __syncthreads();
    }
    // squarings
    for (int it = 0; it < s; it++) {
        for (int e = t; e < 10000; e += NTHR) X[e] = gS[e];
        __syncthreads();
        float2 acc[20];
        if (t < 500) {
#pragma unroll
            for (int q = 0; q < 20; q++) acc[q] = make_float2(0.f, 0.f);
            for (int k = 0; k < 100; k++) {
                float2 xv = X[k * 100 + c];
#pragma unroll
                for (int q = 0; q < 20; q++) cmacc(acc[q], X[(rb * 20 + q) * 100 + k], xv);
            }
        }
        __syncthreads();
        if (t < 500) {
#pragma unroll
            for (int q = 0; q < 20; q++) gS[(rb * 20 + q) * 100 + c] = acc[q];
        }
        __syncthreads();
    }
}

// ---------------- main: whole circuit per batch element in SMEM --------------
__global__ void __launch_bounds__(NTHR, 1) k_main(const float* __restrict__ w_dense,
                                                  const float* __restrict__ b_dense,
                                                  float* __restrict__ out) {
    extern __shared__ float2 sh[];
    float2* st = sh;            // 10000 state
    float2* U  = sh + 10000;    // 10000 staged gate
    __shared__ float2 psi[40];
    __shared__ float redsh[48];

    int tid = threadIdx.x;
    int b = blockIdx.x;

    if (tid < 40) psi[tid] = g_psi[b * 40 + tid];
    __syncthreads();

    // init: outer product of encoded per-wire vectors
    for (int e = tid; e < 10000; e += NTHR) {
        int i0 = e / 1000; int r = e - i0 * 1000;
        int i1 = r / 100;  r -= i1 * 100;
        int i2 = r / 10;   int i3 = r - i2 * 10;
        st[e] = cmul(cmul(psi[i0], psi[10 + i1]), cmul(psi[20 + i2], psi[30 + i3]));
    }
    __syncthreads();

    for (int L = 0; L < 2; L++) {
        // ---- 10 two-mode gates (6 CX then 4 BS) ----
        for (int g = 0; g < 10; g++) {
            if (g == 0 || g == 6) {
                const float4* src = (const float4*)(g == 0 ? g_CX : g_BS);
                float4* dst = (float4*)U;
                for (int e = tid; e < 5000; e += NTHR) dst[e] = src[e];
                __syncthreads();
            }
            int m1 = c_gm1[g], m2 = c_gm2[g];
            int s1 = strd(m1), s2 = strd(m2);
            int wa = 0; while (wa == m1 || wa == m2) wa++;
            int wb = wa + 1; while (wb == m1 || wb == m2) wb++;
            int sa = strd(wa), sb = strd(wb);

            float2 acc[20];
            int base = 0, rb = 0;
            if (tid < 500) {
                rb = tid / 100;
                int sp = tid - rb * 100;
                base = (sp / 10) * sa + (sp % 10) * sb;
#pragma unroll
                for (int q = 0; q < 20; q++) acc[q] = make_float2(0.f, 0.f);
                const float2* Ub = U + rb * 2000;
                for (int kk = 0; kk < 10; kk++) {
                    const float2* rowp = st + base + kk * s1;
                    for (int ll = 0; ll < 10; ll += 2) {
                        float2 x0 = rowp[ll * s2];
                        float2 x1 = rowp[(ll + 1) * s2];
                        const float2* Up = Ub + kk * 10 + ll;
#pragma unroll
                        for (int q = 0; q < 20; q++) {
                            float4 uv = *(const float4*)(Up + q * 100);
                            acc[q].x = fmaf(uv.x, x0.x, fmaf(-uv.y, x0.y, acc[q].x));
                            acc[q].y = fmaf(uv.x, x0.y, fmaf( uv.y, x0.x, acc[q].y));
                            acc[q].x = fmaf(uv.z, x1.x, fmaf(-uv.w, x1.y, acc[q].x));
                            acc[q].y = fmaf(uv.z, x1.y, fmaf( uv.w, x1.x, acc[q].y));
                        }
                    }
                }
            }
            __syncthreads();
            if (tid < 500) {
#pragma unroll
                for (int q = 0; q < 20; q++) {
                    int o = rb * 20 + q;
                    st[base + (o / 10) * s1 + (o % 10) * s2] = acc[q];
                }
            }
            __syncthreads();
        }

        // ---- 4 merged single-mode gates ----
        for (int w = 0; w < 4; w++) {
            if (tid < 100) U[tid] = g_Elay[(L * 4 + w) * 100 + tid];
            __syncthreads();
            int sm = strd(w);
            if (tid < 500) {
                for (int cc = 0; cc < 2; cc++) {
                    int col = tid + cc * 500;
                    int base = (col / sm) * (sm * 10) + (col % sm);
                    float2 in[10];
#pragma unroll
                    for (int k = 0; k < 10; k++) in[k] = st[base + k * sm];
#pragma unroll
                    for (int i = 0; i < 10; i++) {
                        float2 a = make_float2(0.f, 0.f);
#pragma unroll
                        for (int k = 0; k < 10; k++) cmacc(a, U[i * 10 + k], in[k]);
                        st[base + i * sm] = a;
                    }
                }
            }
            __syncthreads();
        }
    }

    // ---- photon-number readout on modes 0..2, dense head ----
    float p0 = 0.f, p1 = 0.f, p2 = 0.f;
    for (int e = tid; e < 10000; e += NTHR) {
        float2 v = st[e];
        float pr = v.x * v.x + v.y * v.y;
        int i0 = e / 1000; int r = e - i0 * 1000;
        int i1 = r / 100;  r -= i1 * 100;
        int i2 = r / 10;
        p0 += pr * (float)i0;
        p1 += pr * (float)i1;
        p2 += pr * (float)i2;
    }
#pragma unroll
    for (int o = 16; o > 0; o >>= 1) {
        p0 += __shfl_down_sync(0xffffffffu, p0, o);
        p1 += __shfl_down_sync(0xffffffffu, p1, o);
        p2 += __shfl_down_sync(0xffffffffu, p2, o);
    }
    int wid = tid >> 5, lane = tid & 31;
    if (lane == 0) { redsh[wid] = p0; redsh[16 + wid] = p1; redsh[32 + wid] = p2; }
    __syncthreads();
    if (tid == 0) {
        float q0 = 0.f, q1 = 0.f, q2 = 0.f;
        for (int w = 0; w < 16; w++) { q0 += redsh[w]; q1 += redsh[16 + w]; q2 += redsh[32 + w]; }
        out[b] = q0 * w_dense[0] + q1 * w_dense[1] + q2 * w_dense[2] + b_dense[0];
    }
}

// ---------------- launch -----------------------------------------------------
extern "C" void kernel_launch(void* const* d_in, const int* in_sizes, int n_in,
                              void* d_out, int out_size) {
    const float* jets    = (const float*)d_in[0];
    const float* s_scale = (const float*)d_in[1];
    const float* dmag    = (const float*)d_in[2];
    const float* dph     = (const float*)d_in[3];
    const float* smag    = (const float*)d_in[4];
    const float* sph     = (const float*)d_in[5];
    const float* w_dense = (const float*)d_in[6];
    const float* b_dense = (const float*)d_in[7];
    float* out = (float*)d_out;

    cudaFuncSetAttribute(k_const100, cudaFuncAttributeMaxDynamicSharedMemorySize, 160000);
    cudaFuncSetAttribute(k_main,     cudaFuncAttributeMaxDynamicSharedMemorySize, 160000);

    k_enc<<<NB * 4 + 8, 128>>>(jets, s_scale, dmag, dph, smag, sph);
    k_const100<<<2, NTHR, 160000>>>();
    k_main<<<NB, NTHR, 160000>>>(w_dense, b_dense, out);
}

// round 5
// speedup vs baseline: 1.2547x; 1.2547x over previous
#include <cuda_runtime.h>
#include <math.h>

#define NB   2048
#define NTHR 512

// ---------------- global scratch -------------------------------------------
__device__ float2 g_psi[NB * 4 * 10];     // encoded per-wire vectors
__device__ float2 g_Elay[8 * 100];        // merged layer 10x10 complex gates (D@S)
__device__ __align__(16) float2 g_CX[10000];   // CX 100x100 complex (dense, proven)
__device__ __align__(16) float2 g_BS[10000];   // BS 100x100 complex (dense, proven)
__device__ __align__(16) float  g_CXr[10000];  // Re(CX)
__device__ float2 g_BSb[670];                  // BS blocks packed from g_BS

// BS block tables: sizes, packed offsets, lo = max(0, N-9)
__device__ const int d_bsz[19] = {1,2,3,4,5,6,7,8,9,10,9,8,7,6,5,4,3,2,1};
__device__ const int d_off[19] = {0,1,5,14,30,55,91,140,204,285,385,466,530,579,615,640,656,665,669};
__device__ const int d_lo[19]  = {0,0,0,0,0,0,0,0,0,0,1,2,3,4,5,6,7,8,9};

// ---------------- complex helpers ------------------------------------------
__device__ __forceinline__ float2 cmul(float2 a, float2 b) {
    return make_float2(a.x * b.x - a.y * b.y, a.x * b.y + a.y * b.x);
}
__device__ __forceinline__ void cmacc(float2& acc, float2 a, float2 b) {
    acc.x = fmaf(a.x, b.x, fmaf(-a.y, b.y, acc.x));
    acc.y = fmaf(a.x, b.y, fmaf( a.y, b.x, acc.y));
}
__device__ __forceinline__ int strd(int w) {
    return w == 0 ? 1000 : (w == 1 ? 100 : (w == 2 ? 10 : 1));
}

// ---------------- 10x10 expm (block-cooperative, >=128 thr) -----------------
__device__ void expm10(float2* X, float2* S, float2* T, float2* T2, float* red, int t) {
    if (t < 10) {
        float s = 0.f;
        for (int j = 0; j < 10; j++) { float2 v = X[t * 10 + j]; s += fabsf(v.x) + fabsf(v.y); }
        red[t] = s;
    }
    __syncthreads();
    if (t == 0) {
        float m = 0.f;
        for (int i = 0; i < 10; i++) m = fmaxf(m, red[i]);
        int s = 0;
        while (m > 0.5f && s < 40) { m *= 0.5f; s++; }
        red[10] = (float)s;
    }
    __syncthreads();
    int s = (int)red[10];
    float sc = ldexpf(1.f, -s);
    if (t < 100) {
        X[t].x *= sc; X[t].y *= sc;
        T[t] = X[t];
        float2 v = X[t];
        if (t % 11 == 0) v.x += 1.f;
        S[t] = v;
    }
    __syncthreads();
    for (int j = 2; j <= 13; j++) {
        float inv = 1.f / (float)j;
        if (t < 100) {
            int i = t / 10, c = t % 10;
            float2 acc = make_float2(0.f, 0.f);
#pragma unroll
            for (int k = 0; k < 10; k++) cmacc(acc, T[i * 10 + k], X[k * 10 + c]);
            T2[t] = make_float2(acc.x * inv, acc.y * inv);
        }
        __syncthreads();
        if (t < 100) { T[t] = T2[t]; S[t].x += T2[t].x; S[t].y += T2[t].y; }
        __syncthreads();
    }
    for (int it = 0; it < s; it++) {
        if (t < 100) {
            int i = t / 10, c = t % 10;
            float2 acc = make_float2(0.f, 0.f);
#pragma unroll
            for (int k = 0; k < 10; k++) cmacc(acc, S[i * 10 + k], S[k * 10 + c]);
            T2[t] = acc;
        }
        __syncthreads();
        if (t < 100) S[t] = T2[t];
        __syncthreads();
    }
}

// ---------------- prep: encoding vectors + layer 10x10 gates ----------------
__global__ void k_enc(const float* __restrict__ jets, const float* __restrict__ s_scale,
                      const float* __restrict__ dmag, const float* __restrict__ dph,
                      const float* __restrict__ smag, const float* __restrict__ sph) {
    __shared__ float2 B0[100], B1[100], B2[100], B3[100], B4[100];
    __shared__ float red[16];
    int t = threadIdx.x;
    int id = blockIdx.x;

    float r_s, p_s, r_d, p_d;
    if (id < NB * 4) {
        const float* j3 = jets + id * 3;
        float eta = j3[0], ph = j3[1], pt = j3[2];
        float sc = 10.f / (1.f + expf(-s_scale[0])) + 0.01f;
        r_s = eta;      p_s = pt * ph * 0.5f;
        r_d = sc * pt;  p_d = eta;
    } else {
        int lw = id - NB * 4;
        r_s = smag[lw]; p_s = sph[lw];
        r_d = dmag[lw]; p_d = dph[lw];
    }

    float2 z = make_float2(r_s * cosf(p_s), r_s * sinf(p_s));
    if (t < 100) {
        int i = t / 10, j = t % 10;
        float2 g = make_float2(0.f, 0.f);
        if (j == i + 2) {
            float v = sqrtf((float)((i + 1) * (i + 2)));
            g.x = 0.5f * z.x * v;  g.y = -0.5f * z.y * v;
        } else if (i == j + 2) {
            float v = sqrtf((float)((j + 1) * (j + 2)));
            g.x = -0.5f * z.x * v; g.y = -0.5f * z.y * v;
        }
        B0[t] = g;
    }
    __syncthreads();
    expm10(B0, B1, B2, B3, red, t);
    __syncthreads();

    float2 al = make_float2(r_d * cosf(p_d), r_d * sinf(p_d));
    if (t < 100) {
        int i = t / 10, j = t % 10;
        float2 g = make_float2(0.f, 0.f);
        if (i == j + 1) {
            float v = sqrtf((float)(j + 1));
            g.x = al.x * v;  g.y = al.y * v;
        } else if (j == i + 1) {
            float v = sqrtf((float)(i + 1));
            g.x = -al.x * v; g.y = al.y * v;
        }
        B0[t] = g;
    }
    __syncthreads();
    expm10(B0, B4, B2, B3, red, t);
    __syncthreads();

    if (id < NB * 4) {
        if (t < 10) {
            float2 acc = make_float2(0.f, 0.f);
#pragma unroll
            for (int k = 0; k < 10; k++) cmacc(acc, B4[t * 10 + k], B1[k * 10 + 0]);
            g_psi[id * 10 + t] = acc;
        }
    } else {
        if (t < 100) {
            int i = t / 10, j = t % 10;
            float2 acc = make_float2(0.f, 0.f);
#pragma unroll
            for (int k = 0; k < 10; k++) cmacc(acc, B4[i * 10 + k], B1[k * 10 + j]);
            g_Elay[(id - NB * 4) * 100 + t] = acc;
        }
    }
}

// ---------------- prep: 100x100 expm of CX / BS (proven R2 code) ------------
__global__ void k_const100() {
    extern __shared__ float2 sh2[];
    float2* X = sh2;            // 10000
    float2* T = sh2 + 10000;    // 10000
    __shared__ float red[128];
    int t = threadIdx.x;
    int m = blockIdx.x;                        // 0 = CX, 1 = BS
    float2* gS = (m == 0) ? g_CX : g_BS;
    const float PIO4 = 0.7853981633974483f;

    for (int e = t; e < 10000; e += NTHR) {
        int o = e / 100, in = e % 100;
        int i = o / 10, j = o % 10, k = in / 10, l = in % 10;
        float2 g = make_float2(0.f, 0.f);
        if (m == 0) {
            float x1 = 0.f;
            if (k == i + 1) x1 = sqrtf((float)(i + 1));
            else if (i == k + 1) x1 = sqrtf((float)(k + 1));
            float y1 = 0.f;
            if (l == j + 1) y1 += sqrtf((float)(j + 1));
            if (j == l + 1) y1 -= sqrtf((float)(l + 1));
            g.x = -0.5f * x1 * y1;
        } else {
            float v = 0.f;
            if (k == i + 1 && j == l + 1) v += sqrtf((float)(i + 1)) * sqrtf((float)(l + 1));
            if (i == k + 1 && l == j + 1) v += sqrtf((float)(k + 1)) * sqrtf((float)(j + 1));
            g.y = PIO4 * v;
        }
        X[e] = g;
    }
    __syncthreads();

    if (t < 100) {
        float s = 0.f;
        for (int q = 0; q < 100; q++) { float2 v = X[t * 100 + q]; s += fabsf(v.x) + fabsf(v.y); }
        red[t] = s;
    }
    __syncthreads();
    if (t == 0) {
        float mx = 0.f;
        for (int i = 0; i < 100; i++) mx = fmaxf(mx, red[i]);
        int s = 0;
        while (mx > 0.5f && s < 40) { mx *= 0.5f; s++; }
        red[0] = (float)s;
    }
    __syncthreads();
    int s = (int)red[0];
    float scf = ldexpf(1.f, -s);

    for (int e = t; e < 10000; e += NTHR) {
        X[e].x *= scf; X[e].y *= scf;
        T[e] = X[e];
        float2 si = X[e];
        if (e / 100 == e % 100) si.x += 1.f;
        gS[e] = si;
    }
    __syncthreads();

    int c = t % 100, rb = t / 100;             // t<500 active in matmuls
    for (int j = 2; j <= 13; j++) {
        float inv = 1.f / (float)j;
        float2 acc[20];
        if (t < 500) {
#pragma unroll
            for (int q = 0; q < 20; q++) acc[q] = make_float2(0.f, 0.f);
            for (int k = 0; k < 100; k++) {
                float2 xv = X[k * 100 + c];
#pragma unroll
                for (int q = 0; q < 20; q++) cmacc(acc[q], T[(rb * 20 + q) * 100 + k], xv);
            }
        }
        __syncthreads();
        if (t < 500) {
#pragma unroll
            for (int q = 0; q < 20; q++) {
                int r = rb * 20 + q;
                float2 v = make_float2(acc[q].x * inv, acc[q].y * inv);
                T[r * 100 + c] = v;
                float2 sv = gS[r * 100 + c];
                sv.x += v.x; sv.y += v.y;
                gS[r * 100 + c] = sv;
            }
        }
        __syncthreads();
    }
    for (int it = 0; it < s; it++) {
        for (int e = t; e < 10000; e += NTHR) X[e] = gS[e];
        __syncthreads();
        float2 acc[20];
        if (t < 500) {
#pragma unroll
            for (int q = 0; q < 20; q++) acc[q] = make_float2(0.f, 0.f);
            for (int k = 0; k < 100; k++) {
                float2 xv = X[k * 100 + c];
#pragma unroll
                for (int q = 0; q < 20; q++) cmacc(acc[q], X[(rb * 20 + q) * 100 + k], xv);
            }
        }
        __syncthreads();
        if (t < 500) {
#pragma unroll
            for (int q = 0; q < 20; q++) gS[(rb * 20 + q) * 100 + c] = acc[q];
        }
        __syncthreads();
    }
}

// ---------------- prep: derive real CX + BS blocks from proven dense --------
__global__ void k_pack() {
    int t = blockIdx.x * blockDim.x + threadIdx.x;
    if (t < 10000) {
        g_CXr[t] = g_CX[t].x;                 // CX is exactly real
    } else if (t < 11900) {
        int e = t - 10000;                    // (N, r, c) over 19 x 10 x 10
        int N = e / 100, rc = e % 100;
        int r = rc / 10, cc = rc % 10;
        int b = d_bsz[N], lo = d_lo[N];
        if (r < b && cc < b) {
            int i = lo + r,  j = N - i;       // out (m1,m2)
            int k = lo + cc, l = N - k;       // in  (m1,m2)
            g_BSb[d_off[N] + r * b + cc] = g_BS[(i * 10 + j) * 100 + (k * 10 + l)];
        }
    }
}

// ---------------- main kernel passes ----------------------------------------
// Real two-mode gate (CX): R2's proven dense pass with real U.
template<int S1, int S2, int SA, int SB>
__device__ __forceinline__ void pass_cx(float2* st, const float* U, int tid) {
    float2 acc[20];
    int base = 0, rb = 0;
    if (tid < 500) {
        rb = tid / 100;
        int sp = tid - rb * 100;
        base = (sp / 10) * SA + (sp % 10) * SB;
#pragma unroll
        for (int q = 0; q < 20; q++) acc[q] = make_float2(0.f, 0.f);
        const float* Ub = U + rb * 2000;
        for (int kk = 0; kk < 10; kk++) {
            const float2* rowp = st + base + kk * S1;
#pragma unroll
            for (int ll = 0; ll < 10; ll += 2) {
                float2 x0 = rowp[ll * S2];
                float2 x1 = rowp[(ll + 1) * S2];
                const float* Up = Ub + kk * 10 + ll;
#pragma unroll
                for (int q = 0; q < 20; q++) {
                    float2 uv = *(const float2*)(Up + q * 100);
                    acc[q].x = fmaf(uv.x, x0.x, acc[q].x);
                    acc[q].y = fmaf(uv.x, x0.y, acc[q].y);
                    acc[q].x = fmaf(uv.y, x1.x, acc[q].x);
                    acc[q].y = fmaf(uv.y, x1.y, acc[q].y);
                }
            }
        }
    }
    __syncthreads();
    if (tid < 500) {
#pragma unroll
        for (int q = 0; q < 20; q++) {
            int o = rb * 20 + q;
            st[base + (o / 10) * S1 + (o % 10) * S2] = acc[q];
        }
    }
    __syncthreads();
}

// BS photon-number-block pass. SI/SJ = strides of m1/m2; SA/SB spectators.
template<int SI, int SJ, int SA, int SB>
__device__ __forceinline__ void pass_bs(float2* st, const float2* BSb, int tid) {
    for (int it = tid; it < 1900; it += NTHR) {
        int N = it / 100; int sp = it - N * 100;
        int b = d_bsz[N], lo = d_lo[N], of = d_off[N];
        int spa = sp / 10;
        int base = spa * SA + (sp - spa * 10) * SB;
        int ilo = base + lo * SI + (N - lo) * SJ;
        const int step = SI - SJ;
        float2 in[10];
        for (int c = 0; c < b; c++) in[c] = st[ilo + c * step];
        const float2* Bb = BSb + of;
        for (int r = 0; r < b; r++) {
            float2 acc = make_float2(0.f, 0.f);
            const float2* Br = Bb + r * b;
            for (int c = 0; c < b; c++) cmacc(acc, Br[c], in[c]);
            st[ilo + r * step] = acc;
        }
    }
    __syncthreads();
}

// ---------------- main: whole circuit per batch element in SMEM -------------
// SMEM floats: st[20000] | CXr[10000] | BSb 1340 | Ue 200
#define SM_CXR 20000
#define SM_BSB 30000
#define SM_UE  31340
#define SM_FLOATS 31544

__global__ void __launch_bounds__(NTHR) k_main(const float* __restrict__ w_dense,
                                               const float* __restrict__ b_dense,
                                               float* __restrict__ out) {
    extern __shared__ float shf[];
    float2* st  = (float2*)shf;
    float*  CXr = shf + SM_CXR;
    float2* BSb = (float2*)(shf + SM_BSB);
    float2* Ue  = (float2*)(shf + SM_UE);
    __shared__ float2 psi[40];
    __shared__ float redsh[48];

    int tid = threadIdx.x;
    int b = blockIdx.x;

    // ---- load tables (CX staged ONCE; reused for all 12 CX applications) ----
    {
        const float4* src = (const float4*)g_CXr;
        float4* dst = (float4*)CXr;
        for (int e = tid; e < 2500; e += NTHR) dst[e] = src[e];
    }
    for (int idx = tid; idx < 670; idx += NTHR) BSb[idx] = g_BSb[idx];
    if (tid < 40) psi[tid] = g_psi[b * 40 + tid];
    __syncthreads();

    // ---- init: outer product of encoded per-wire vectors ----
    for (int e = tid; e < 10000; e += NTHR) {
        int i0 = e / 1000; int r = e - i0 * 1000;
        int i1 = r / 100;  r -= i1 * 100;
        int i2 = r / 10;   int i3 = r - i2 * 10;
        st[e] = cmul(cmul(psi[i0], psi[10 + i1]), cmul(psi[20 + i2], psi[30 + i3]));
    }
    __syncthreads();

#pragma unroll 1
    for (int L = 0; L < 2; L++) {
        // ---- 6 CX gates (real dense), reference order ----
        pass_cx<1000, 100, 10, 1>(st, CXr, tid);    // (0,1)
        pass_cx<1000, 10, 100, 1>(st, CXr, tid);    // (0,2)
        pass_cx<1000, 1, 100, 10>(st, CXr, tid);    // (0,3)
        pass_cx<100, 10, 1000, 1>(st, CXr, tid);    // (1,2)
        pass_cx<100, 1, 1000, 10>(st, CXr, tid);    // (1,3)
        pass_cx<10, 1, 1000, 100>(st, CXr, tid);    // (2,3)

        // ---- 4 BS gates (photon-number blocks) ----
        pass_bs<1000, 100, 10, 1>(st, BSb, tid);    // (0,1)
        pass_bs<100, 10, 1000, 1>(st, BSb, tid);    // (1,2)
        pass_bs<10, 1, 1000, 100>(st, BSb, tid);    // (2,3)
        pass_bs<1, 1000, 100, 10>(st, BSb, tid);    // (3,0)

        // ---- 4 merged single-mode E = D@S gates (R2-proven code) ----
        for (int w = 0; w < 4; w++) {
            if (tid < 100) Ue[tid] = g_Elay[(L * 4 + w) * 100 + tid];
            __syncthreads();
            int sm = strd(w);
            if (tid < 500) {
                for (int cc = 0; cc < 2; cc++) {
                    int col = tid + cc * 500;
                    int base = (col / sm) * (sm * 10) + (col % sm);
                    float2 in[10];
#pragma unroll
                    for (int k = 0; k < 10; k++) in[k] = st[base + k * sm];
#pragma unroll
                    for (int i = 0; i < 10; i++) {
                        float2 a = make_float2(0.f, 0.f);
#pragma unroll
                        for (int k = 0; k < 10; k++) cmacc(a, Ue[i * 10 + k], in[k]);
                        st[base + i * sm] = a;
                    }
                }
            }
            __syncthreads();
        }
    }

    // ---- photon-number readout on modes 0..2, dense head ----
    float p0 = 0.f, p1 = 0.f, p2 = 0.f;
    for (int e = tid; e < 10000; e += NTHR) {
        float2 v = st[e];
        float pr = v.x * v.x + v.y * v.y;
        int i0 = e / 1000; int r = e - i0 * 1000;
        int i1 = r / 100;  r -= i1 * 100;
        int i2 = r / 10;
        p0 += pr * (float)i0;
        p1 += pr * (float)i1;
        p2 += pr * (float)i2;
    }
#pragma unroll
    for (int o = 16; o > 0; o >>= 1) {
        p0 += __shfl_down_sync(0xffffffffu, p0, o);
        p1 += __shfl_down_sync(0xffffffffu, p1, o);
        p2 += __shfl_down_sync(0xffffffffu, p2, o);
    }
    int wid = tid >> 5, lane = tid & 31;
    if (lane == 0) { redsh[wid] = p0; redsh[16 + wid] = p1; redsh[32 + wid] = p2; }
    __syncthreads();
    if (tid == 0) {
        float q0 = 0.f, q1 = 0.f, q2 = 0.f;
        for (int w = 0; w < 16; w++) { q0 += redsh[w]; q1 += redsh[16 + w]; q2 += redsh[32 + w]; }
        out[b] = q0 * w_dense[0] + q1 * w_dense[1] + q2 * w_dense[2] + b_dense[0];
    }
}

// ---------------- launch -----------------------------------------------------
extern "C" void kernel_launch(void* const* d_in, const int* in_sizes, int n_in,
                              void* d_out, int out_size) {
    const float* jets    = (const float*)d_in[0];
    const float* s_scale = (const float*)d_in[1];
    const float* dmag    = (const float*)d_in[2];
    const float* dph     = (const float*)d_in[3];
    const float* smag    = (const float*)d_in[4];
    const float* sph     = (const float*)d_in[5];
    const float* w_dense = (const float*)d_in[6];
    const float* b_dense = (const float*)d_in[7];
    float* out = (float*)d_out;

    const int smem_main = SM_FLOATS * 4;   // 126176 bytes
    cudaFuncSetAttribute(k_const100, cudaFuncAttributeMaxDynamicSharedMemorySize, 160000);
    cudaFuncSetAttribute(k_main,     cudaFuncAttributeMaxDynamicSharedMemorySize, smem_main);

    k_enc<<<NB * 4 + 8, 128>>>(jets, s_scale, dmag, dph, smag, sph);
    k_const100<<<2, NTHR, 160000>>>();
    k_pack<<<47, 256>>>();
    k_main<<<NB, NTHR, smem_main>>>(w_dense, b_dense, out);
}

// round 6
// speedup vs baseline: 1.6622x; 1.3249x over previous
#include <cuda_runtime.h>
#include <math.h>

#define NB   2048
#define NTHR 1024

// ---------------- global scratch -------------------------------------------
__device__ float2 g_psi[NB * 4 * 10];       // encoded per-wire vectors
__device__ float2 g_Elay[8 * 100];          // merged layer 10x10 complex gates (D@S)
__device__ __align__(16) float2 g_Xm[2][10000];   // scaled generators (CX, BS)
__device__ __align__(16) float2 g_Tp[2][2][10000];// Taylor term ping-pong [parity][m]
__device__ __align__(16) float2 g_Sp[2][2][10000];// partial sum ping-pong [parity][m]
__device__ __align__(16) float  g_CXp[12000];     // CX real, packed [k1][o][12]
__device__ float2 g_BSb[670];                     // BS photon-number blocks packed

// BS block tables: sizes, packed offsets, lo = max(0, N-9)
__device__ const int d_bsz[19] = {1,2,3,4,5,6,7,8,9,10,9,8,7,6,5,4,3,2,1};
__device__ const int d_off[19] = {0,1,5,14,30,55,91,140,204,285,385,466,530,579,615,640,656,665,669};
__device__ const int d_lo[19]  = {0,0,0,0,0,0,0,0,0,0,1,2,3,4,5,6,7,8,9};

// ---------------- complex helpers ------------------------------------------
__device__ __forceinline__ float2 cmul(float2 a, float2 b) {
    return make_float2(a.x * b.x - a.y * b.y, a.x * b.y + a.y * b.x);
}
__device__ __forceinline__ void cmacc(float2& acc, float2 a, float2 b) {
    acc.x = fmaf(a.x, b.x, fmaf(-a.y, b.y, acc.x));
    acc.y = fmaf(a.x, b.y, fmaf( a.y, b.x, acc.y));
}
__device__ __forceinline__ int strd(int w) {
    return w == 0 ? 1000 : (w == 1 ? 100 : (w == 2 ? 10 : 1));
}

// ---------------- 10x10 expm (block-cooperative, >=128 thr) -----------------
__device__ void expm10(float2* X, float2* S, float2* T, float2* T2, float* red, int t) {
    if (t < 10) {
        float s = 0.f;
        for (int j = 0; j < 10; j++) { float2 v = X[t * 10 + j]; s += fabsf(v.x) + fabsf(v.y); }
        red[t] = s;
    }
    __syncthreads();
    if (t == 0) {
        float m = 0.f;
        for (int i = 0; i < 10; i++) m = fmaxf(m, red[i]);
        int s = 0;
        while (m > 0.5f && s < 40) { m *= 0.5f; s++; }
        red[10] = (float)s;
    }
    __syncthreads();
    int s = (int)red[10];
    float sc = ldexpf(1.f, -s);
    if (t < 100) {
        X[t].x *= sc; X[t].y *= sc;
        T[t] = X[t];
        float2 v = X[t];
        if (t % 11 == 0) v.x += 1.f;
        S[t] = v;
    }
    __syncthreads();
    for (int j = 2; j <= 13; j++) {
        float inv = 1.f / (float)j;
        if (t < 100) {
            int i = t / 10, c = t % 10;
            float2 acc = make_float2(0.f, 0.f);
#pragma unroll
            for (int k = 0; k < 10; k++) cmacc(acc, T[i * 10 + k], X[k * 10 + c]);
            T2[t] = make_float2(acc.x * inv, acc.y * inv);
        }
        __syncthreads();
        if (t < 100) { T[t] = T2[t]; S[t].x += T2[t].x; S[t].y += T2[t].y; }
        __syncthreads();
    }
    for (int it = 0; it < s; it++) {
        if (t < 100) {
            int i = t / 10, c = t % 10;
            float2 acc = make_float2(0.f, 0.f);
#pragma unroll
            for (int k = 0; k < 10; k++) cmacc(acc, S[i * 10 + k], S[k * 10 + c]);
            T2[t] = acc;
        }
        __syncthreads();
        if (t < 100) S[t] = T2[t];
        __syncthreads();
    }
}

// ---------------- prep: encoding vectors + layer 10x10 gates ----------------
__global__ void k_enc(const float* __restrict__ jets, const float* __restrict__ s_scale,
                      const float* __restrict__ dmag, const float* __restrict__ dph,
                      const float* __restrict__ smag, const float* __restrict__ sph) {
    __shared__ float2 B0[100], B1[100], B2[100], B3[100], B4[100];
    __shared__ float red[16];
    int t = threadIdx.x;
    int id = blockIdx.x;

    float r_s, p_s, r_d, p_d;
    if (id < NB * 4) {
        const float* j3 = jets + id * 3;
        float eta = j3[0], ph = j3[1], pt = j3[2];
        float sc = 10.f / (1.f + expf(-s_scale[0])) + 0.01f;
        r_s = eta;      p_s = pt * ph * 0.5f;
        r_d = sc * pt;  p_d = eta;
    } else {
        int lw = id - NB * 4;
        r_s = smag[lw]; p_s = sph[lw];
        r_d = dmag[lw]; p_d = dph[lw];
    }

    float2 z = make_float2(r_s * cosf(p_s), r_s * sinf(p_s));
    if (t < 100) {
        int i = t / 10, j = t % 10;
        float2 g = make_float2(0.f, 0.f);
        if (j == i + 2) {
            float v = sqrtf((float)((i + 1) * (i + 2)));
            g.x = 0.5f * z.x * v;  g.y = -0.5f * z.y * v;
        } else if (i == j + 2) {
            float v = sqrtf((float)((j + 1) * (j + 2)));
            g.x = -0.5f * z.x * v; g.y = -0.5f * z.y * v;
        }
        B0[t] = g;
    }
    __syncthreads();
    expm10(B0, B1, B2, B3, red, t);
    __syncthreads();

    float2 al = make_float2(r_d * cosf(p_d), r_d * sinf(p_d));
    if (t < 100) {
        int i = t / 10, j = t % 10;
        float2 g = make_float2(0.f, 0.f);
        if (i == j + 1) {
            float v = sqrtf((float)(j + 1));
            g.x = al.x * v;  g.y = al.y * v;
        } else if (j == i + 1) {
            float v = sqrtf((float)(i + 1));
            g.x = -al.x * v; g.y = al.y * v;
        }
        B0[t] = g;
    }
    __syncthreads();
    expm10(B0, B4, B2, B3, red, t);
    __syncthreads();

    if (id < NB * 4) {
        if (t < 10) {
            float2 acc = make_float2(0.f, 0.f);
#pragma unroll
            for (int k = 0; k < 10; k++) cmacc(acc, B4[t * 10 + k], B1[k * 10 + 0]);
            g_psi[id * 10 + t] = acc;
        }
    } else {
        if (t < 100) {
            int i = t / 10, j = t % 10;
            float2 acc = make_float2(0.f, 0.f);
#pragma unroll
            for (int k = 0; k < 10; k++) cmacc(acc, B4[i * 10 + k], B1[k * 10 + j]);
            g_Elay[(id - NB * 4) * 100 + t] = acc;
        }
    }
}

// ---------------- prep pipeline: 100x100 expm via parallel launches ---------
// Fixed scaling 1/64 (scaled norms: CX<=0.32, BS<=0.25 < 0.5) + Taylor-13 + 6 squarings.
__global__ void k_g_init() {
    int m = blockIdx.x;            // 0 = CX, 1 = BS
    int t = threadIdx.x;
    const float PIO4 = 0.7853981633974483f;
    const float SCF = 1.0f / 64.0f;
    for (int e = t; e < 10000; e += blockDim.x) {
        int o = e / 100, in = e % 100;
        int i = o / 10, j = o % 10, k = in / 10, l = in % 10;
        float2 g = make_float2(0.f, 0.f);
        if (m == 0) {
            float x1 = 0.f;
            if (k == i + 1) x1 = sqrtf((float)(i + 1));
            else if (i == k + 1) x1 = sqrtf((float)(k + 1));
            float y1 = 0.f;
            if (l == j + 1) y1 += sqrtf((float)(j + 1));
            if (j == l + 1) y1 -= sqrtf((float)(l + 1));
            g.x = -0.5f * x1 * y1;
        } else {
            float v = 0.f;
            if (k == i + 1 && j == l + 1) v += sqrtf((float)(i + 1)) * sqrtf((float)(l + 1));
            if (i == k + 1 && l == j + 1) v += sqrtf((float)(k + 1)) * sqrtf((float)(j + 1));
            g.y = PIO4 * v;
        }
        g.x *= SCF; g.y *= SCF;
        g_Xm[m][e] = g;
        g_Tp[0][m][e] = g;
        float2 s = g;
        if (o == in) s.x += 1.f;
        g_Sp[0][m][e] = s;
    }
}

// T_new = T_old @ X / j ; S += T_new.  grid 40: (m = b/20, rowblock = b%20, 5 rows)
__global__ void k_g_taylor(int jterm, int par) {
    int t = threadIdx.x;
    if (t >= 500) return;
    int m = blockIdx.x / 20, rblk = blockIdx.x % 20;
    int row = rblk * 5 + t / 100, col = t % 100;
    const float2* T = g_Tp[par][m];
    const float2* X = g_Xm[m];
    float inv = 1.f / (float)jterm;
    float2 acc = make_float2(0.f, 0.f);
    for (int k = 0; k < 100; k++) cmacc(acc, T[row * 100 + k], X[k * 100 + col]);
    acc.x *= inv; acc.y *= inv;
    g_Tp[1 - par][m][row * 100 + col] = acc;
    float2 s = g_Sp[0][m][row * 100 + col];
    s.x += acc.x; s.y += acc.y;
    g_Sp[0][m][row * 100 + col] = s;
}

// S_new = S_old @ S_old. parity sequence 0,1,0,1,0,1 -> final result in g_Sp[0].
__global__ void k_g_square(int par) {
    int t = threadIdx.x;
    if (t >= 500) return;
    int m = blockIdx.x / 20, rblk = blockIdx.x % 20;
    int row = rblk * 5 + t / 100, col = t % 100;
    const float2* S = g_Sp[par][m];
    float2 acc = make_float2(0.f, 0.f);
    for (int k = 0; k < 100; k++) cmacc(acc, S[row * 100 + k], S[k * 100 + col]);
    g_Sp[1 - par][m][row * 100 + col] = acc;
}

// ---------------- prep: pack CX real [k1][o][12] + BS blocks ----------------
__global__ void k_pack() {
    int t = blockIdx.x * blockDim.x + threadIdx.x;
    if (t < 12000) {
        int kk = t / 1200, rem = t % 1200;
        int o = rem / 12, ll = rem % 12;
        g_CXp[t] = (ll < 10) ? g_Sp[0][0][o * 100 + kk * 10 + ll].x : 0.f;
    } else if (t < 13900) {
        int e = t - 12000;                    // (N, r, c) over 19 x 10 x 10
        int N = e / 100, rc = e % 100;
        int r = rc / 10, cc = rc % 10;
        int b = d_bsz[N], lo = d_lo[N];
        if (r < b && cc < b) {
            int i = lo + r,  j = N - i;       // out (m1,m2)
            int k = lo + cc, l = N - k;       // in  (m1,m2)
            g_BSb[d_off[N] + r * b + cc] = g_Sp[0][1][(i * 10 + j) * 100 + (k * 10 + l)];
        }
    }
}

// ---------------- main kernel passes ----------------------------------------
// Real two-mode CX gate. U packed [k1][o][12]; each thread: 10 outputs.
template<int S1, int S2, int SA, int SB>
__device__ __forceinline__ void pass_cx(float2* st, const float* Up, int tid) {
    float2 acc[10];
    int base = 0, rb = 0;
    if (tid < 1000) {
        rb = tid / 100;
        int sp = tid - rb * 100;
        base = (sp / 10) * SA + (sp % 10) * SB;
#pragma unroll
        for (int q = 0; q < 10; q++) acc[q] = make_float2(0.f, 0.f);
#pragma unroll 1
        for (int kk = 0; kk < 10; kk++) {
            float2 xr[10];
            const float2* rowp = st + base + kk * S1;
#pragma unroll
            for (int ll = 0; ll < 10; ll++) xr[ll] = rowp[ll * S2];
            const float* Uk = Up + kk * 1200 + rb * 120;
#pragma unroll
            for (int q = 0; q < 10; q++) {
                const float* Ur = Uk + q * 12;
                float4 u0 = *(const float4*)Ur;
                float4 u1 = *(const float4*)(Ur + 4);
                float2 u2 = *(const float2*)(Ur + 8);
                float ax = acc[q].x, ay = acc[q].y;
                ax = fmaf(u0.x, xr[0].x, ax); ay = fmaf(u0.x, xr[0].y, ay);
                ax = fmaf(u0.y, xr[1].x, ax); ay = fmaf(u0.y, xr[1].y, ay);
                ax = fmaf(u0.z, xr[2].x, ax); ay = fmaf(u0.z, xr[2].y, ay);
                ax = fmaf(u0.w, xr[3].x, ax); ay = fmaf(u0.w, xr[3].y, ay);
                ax = fmaf(u1.x, xr[4].x, ax); ay = fmaf(u1.x, xr[4].y, ay);
                ax = fmaf(u1.y, xr[5].x, ax); ay = fmaf(u1.y, xr[5].y, ay);
                ax = fmaf(u1.z, xr[6].x, ax); ay = fmaf(u1.z, xr[6].y, ay);
                ax = fmaf(u1.w, xr[7].x, ax); ay = fmaf(u1.w, xr[7].y, ay);
                ax = fmaf(u2.x, xr[8].x, ax); ay = fmaf(u2.x, xr[8].y, ay);
                ax = fmaf(u2.y, xr[9].x, ax); ay = fmaf(u2.y, xr[9].y, ay);
                acc[q].x = ax; acc[q].y = ay;
            }
        }
    }
    __syncthreads();
    if (tid < 1000) {
#pragma unroll
        for (int q = 0; q < 10; q++)
            st[base + rb * S1 + q * S2] = acc[q];
    }
    __syncthreads();
}

// BS photon-number-block pass. SI/SJ = strides of m1/m2; SA/SB spectators.
template<int SI, int SJ, int SA, int SB>
__device__ __forceinline__ void pass_bs(float2* st, const float2* BSb, int tid) {
    for (int it = tid; it < 1900; it += NTHR) {
        int N = it / 100; int sp = it - N * 100;
        int b = d_bsz[N], lo = d_lo[N], of = d_off[N];
        int spa = sp / 10;
        int base = spa * SA + (sp - spa * 10) * SB;
        int ilo = base + lo * SI + (N - lo) * SJ;
        const int step = SI - SJ;
        float2 in[10];
        for (int c = 0; c < b; c++) in[c] = st[ilo + c * step];
        const float2* Bb = BSb + of;
        for (int r = 0; r < b; r++) {
            float2 acc = make_float2(0.f, 0.f);
            const float2* Br = Bb + r * b;
            for (int c = 0; c < b; c++) cmacc(acc, Br[c], in[c]);
            st[ilo + r * step] = acc;
        }
    }
    __syncthreads();
}

// Complex single-mode gate, in-place per fiber.
__device__ __forceinline__ void pass_e(float2* st, const float2* E, int sm, int tid) {
    if (tid < 1000) {
        int base = (tid / sm) * (sm * 10) + (tid % sm);
        float2 in[10];
#pragma unroll
        for (int k = 0; k < 10; k++) in[k] = st[base + k * sm];
#pragma unroll
        for (int i = 0; i < 10; i++) {
            float2 a = make_float2(0.f, 0.f);
#pragma unroll
            for (int k = 0; k < 10; k++) cmacc(a, E[i * 10 + k], in[k]);
            st[base + i * sm] = a;
        }
    }
    __syncthreads();
}

// ---------------- main: whole circuit per batch element in SMEM -------------
// SMEM floats: st[20000] | Up[12000] | BSb[1340] | Eg[1600]
#define SM_UP  20000
#define SM_BSB 32000
#define SM_EG  33340
#define SM_FLOATS 34940

__global__ void __launch_bounds__(NTHR, 1) k_main(const float* __restrict__ w_dense,
                                                  const float* __restrict__ b_dense,
                                                  float* __restrict__ out) {
    extern __shared__ float shf[];
    float2* st  = (float2*)shf;
    float*  Up  = shf + SM_UP;
    float2* BSb = (float2*)(shf + SM_BSB);
    float2* Eg  = (float2*)(shf + SM_EG);
    __shared__ float2 psi[40];
    __shared__ float redsh[96];

    int tid = threadIdx.x;
    int b = blockIdx.x;

    // ---- stage all tables once ----
    {
        const float4* src = (const float4*)g_CXp;
        float4* dst = (float4*)Up;
        for (int e = tid; e < 3000; e += NTHR) dst[e] = src[e];
    }
    for (int idx = tid; idx < 670; idx += NTHR) BSb[idx] = g_BSb[idx];
    for (int idx = tid; idx < 800; idx += NTHR) Eg[idx] = g_Elay[idx];
    if (tid < 40) psi[tid] = g_psi[b * 40 + tid];
    __syncthreads();

    // ---- init: outer product of encoded per-wire vectors ----
    for (int e = tid; e < 10000; e += NTHR) {
        int i0 = e / 1000; int r = e - i0 * 1000;
        int i1 = r / 100;  r -= i1 * 100;
        int i2 = r / 10;   int i3 = r - i2 * 10;
        st[e] = cmul(cmul(psi[i0], psi[10 + i1]), cmul(psi[20 + i2], psi[30 + i3]));
    }
    __syncthreads();

#pragma unroll 1
    for (int L = 0; L < 2; L++) {
        // ---- 6 CX gates (real, packed U), reference order ----
        pass_cx<1000, 100, 10, 1>(st, Up, tid);    // (0,1)
        pass_cx<1000, 10, 100, 1>(st, Up, tid);    // (0,2)
        pass_cx<1000, 1, 100, 10>(st, Up, tid);    // (0,3)
        pass_cx<100, 10, 1000, 1>(st, Up, tid);    // (1,2)
        pass_cx<100, 1, 1000, 10>(st, Up, tid);    // (1,3)
        pass_cx<10, 1, 1000, 100>(st, Up, tid);    // (2,3)

        // ---- 4 BS gates (photon-number blocks) ----
        pass_bs<1000, 100, 10, 1>(st, BSb, tid);   // (0,1)
        pass_bs<100, 10, 1000, 1>(st, BSb, tid);   // (1,2)
        pass_bs<10, 1, 1000, 100>(st, BSb, tid);   // (2,3)
        pass_bs<1, 1000, 100, 10>(st, BSb, tid);   // (3,0)

        // ---- 4 merged single-mode E = D@S gates ----
        pass_e(st, Eg + (L * 4 + 0) * 100, 1000, tid);
        pass_e(st, Eg + (L * 4 + 1) * 100, 100,  tid);
        pass_e(st, Eg + (L * 4 + 2) * 100, 10,   tid);
        pass_e(st, Eg + (L * 4 + 3) * 100, 1,    tid);
    }

    // ---- photon-number readout on modes 0..2, dense head ----
    float p0 = 0.f, p1 = 0.f, p2 = 0.f;
    for (int e = tid; e < 10000; e += NTHR) {
        float2 v = st[e];
        float pr = v.x * v.x + v.y * v.y;
        int i0 = e / 1000; int r = e - i0 * 1000;
        int i1 = r / 100;  r -= i1 * 100;
        int i2 = r / 10;
        p0 += pr * (float)i0;
        p1 += pr * (float)i1;
        p2 += pr * (float)i2;
    }
#pragma unroll
    for (int o = 16; o > 0; o >>= 1) {
        p0 += __shfl_down_sync(0xffffffffu, p0, o);
        p1 += __shfl_down_sync(0xffffffffu, p1, o);
        p2 += __shfl_down_sync(0xffffffffu, p2, o);
    }
    int wid = tid >> 5, lane = tid & 31;
    if (lane == 0) { redsh[wid] = p0; redsh[32 + wid] = p1; redsh[64 + wid] = p2; }
    __syncthreads();
    if (tid == 0) {
        float q0 = 0.f, q1 = 0.f, q2 = 0.f;
        for (int w = 0; w < 32; w++) { q0 += redsh[w]; q1 += redsh[32 + w]; q2 += redsh[64 + w]; }
        out[b] = q0 * w_dense[0] + q1 * w_dense[1] + q2 * w_dense[2] + b_dense[0];
    }
}

// ---------------- launch -----------------------------------------------------
extern "C" void kernel_launch(void* const* d_in, const int* in_sizes, int n_in,
                              void* d_out, int out_size) {
    const float* jets    = (const float*)d_in[0];
    const float* s_scale = (const float*)d_in[1];
    const float* dmag    = (const float*)d_in[2];
    const float* dph     = (const float*)d_in[3];
    const float* smag    = (const float*)d_in[4];
    const float* sph     = (const float*)d_in[5];
    const float* w_dense = (const float*)d_in[6];
    const float* b_dense = (const float*)d_in[7];
    float* out = (float*)d_out;

    const int smem_main = SM_FLOATS * 4;   // 139760 bytes
    cudaFuncSetAttribute(k_main, cudaFuncAttributeMaxDynamicSharedMemorySize, smem_main);

    k_enc<<<NB * 4 + 8, 128>>>(jets, s_scale, dmag, dph, smag, sph);
    k_g_init<<<2, 512>>>();
    for (int j = 2; j <= 13; j++)
        k_g_taylor<<<40, 512>>>(j, j & 1);          // j=2 reads parity 0
    for (int it = 0; it < 6; it++)
        k_g_square<<<40, 512>>>(it & 1);            // final result in g_Sp[0]
    k_pack<<<55, 256>>>();
    k_main<<<NB, NTHR, smem_main>>>(w_dense, b_dense, out);
}